// round 16
// baseline (speedup 1.0000x reference)
#include <cuda_runtime.h>
#include <cuda_fp16.h>
#include <cstdint>
#include <math.h>

#define NTOK 16384
#define HDIM 1024
#define IDIM 2048
#define NEXP 8
#define NSLOT (2*NTOK)

// ---------------- PTX helpers (plain sm_103-safe) ----------------
__device__ __forceinline__ uint32_t smem_u32(const void* p) {
    uint32_t a;
    asm("{ .reg .u64 t; cvta.to.shared.u64 t, %1; cvt.u32.u64 %0, t; }" : "=r"(a) : "l"(p));
    return a;
}
#define CP16(dst, src) asm volatile("cp.async.cg.shared.global [%0], [%1], 16;" :: "r"(dst), "l"(src))
#define CP_COMMIT() asm volatile("cp.async.commit_group;" ::: "memory")
#define CP_WAIT1()  asm volatile("cp.async.wait_group 1;" ::: "memory")
#define CP_WAIT0()  asm volatile("cp.async.wait_group 0;" ::: "memory")
#define LDSM4(r0, r1, r2, r3, a) \
    asm volatile("ldmatrix.sync.aligned.m8n8.x4.shared.b16 {%0,%1,%2,%3}, [%4];" \
        : "=r"(r0), "=r"(r1), "=r"(r2), "=r"(r3) : "r"(a))

__device__ __forceinline__ void mma_f16(float d[4], const uint32_t a[4], const uint32_t b[2]) {
    asm volatile("mma.sync.aligned.m16n8k16.row.col.f32.f16.f16.f32 "
        "{%0,%1,%2,%3}, {%4,%5,%6,%7}, {%8,%9}, {%0,%1,%2,%3};"
        : "+f"(d[0]), "+f"(d[1]), "+f"(d[2]), "+f"(d[3])
        : "r"(a[0]), "r"(a[1]), "r"(a[2]), "r"(a[3]), "r"(b[0]), "r"(b[1]));
}

// SMEM: 128B rows (64 fp16), 16B-chunk XOR swizzle.
__device__ __forceinline__ uint32_t swoff(int row, int kb) {
    return (uint32_t)(row * 128 + ((((kb) >> 4) ^ (row & 7)) << 4) + ((kb) & 15));
}

// ldmatrix x4 of a 16x16 fp16 tile at (row base mrow, k-byte base kb).
__device__ __forceinline__ void ldm16x16(uint32_t T, int mrow, int kb, int lane, uint32_t r[4]) {
    int mat = lane >> 3, lr = lane & 7;
    uint32_t addr = T + swoff(mrow + (mat & 1) * 8 + lr, kb + (mat >> 1) * 16);
    LDSM4(r[0], r[1], r[2], r[3], addr);
}

// ---------------- device scratch ----------------
__device__ int   g_count[NEXP];
__device__ int   g_base[NEXP + 1];
__device__ int   g_perm[NEXP * NTOK];
__device__ int   g_tokexp[NSLOT];
__device__ int   g_tokpos[NSLOT];
__device__ float g_tokw[NSLOT];
__device__ __half g_Xh[(size_t)NTOK * HDIM];
__device__ __half g_Gh[(size_t)NEXP * IDIM * HDIM];
__device__ __half g_Uh[(size_t)NEXP * IDIM * HDIM];
__device__ __half g_Dh[(size_t)NEXP * HDIM * IDIM];
__device__ __half g_Hh[(size_t)NSLOT * IDIM];
__device__ float g_y[(size_t)NSLOT * HDIM];

// ---------------- small kernels ----------------
__global__ void zero_counts_kernel() { if (threadIdx.x < NEXP) g_count[threadIdx.x] = 0; }

__global__ void scan_base_kernel() {
    int b = 0; g_base[0] = 0;
    #pragma unroll
    for (int e = 0; e < NEXP; e++) { b += g_count[e]; g_base[e + 1] = b; }
}

// fp32 -> single fp16 (weights)
__global__ void convert1_kernel(const float* __restrict__ s, __half* __restrict__ h, int n4) {
    int i = blockIdx.x * blockDim.x + threadIdx.x;
    if (i >= n4) return;
    float4 v = reinterpret_cast<const float4*>(s)[i];
    __half o[4] = {__float2half_rn(v.x), __float2half_rn(v.y),
                   __float2half_rn(v.z), __float2half_rn(v.w)};
    reinterpret_cast<uint2*>(h)[i] = *reinterpret_cast<uint2*>(o);
}

// ---------------- router (also emits X as fp16) ----------------
__global__ void router_kernel(const float* __restrict__ X, const float* __restrict__ RW) {
    int gwarp = (blockIdx.x * blockDim.x + threadIdx.x) >> 5;
    int lane  = threadIdx.x & 31;
    if (gwarp >= NTOK) return;
    const float4* x4 = reinterpret_cast<const float4*>(X + (size_t)gwarp * HDIM);

    float4 xr[8];
    #pragma unroll
    for (int i = 0; i < 8; i++) xr[i] = x4[lane + 32 * i];

    // fused X -> fp16 store
    {
        __half* xh = g_Xh + (size_t)gwarp * HDIM;
        #pragma unroll
        for (int i = 0; i < 8; i++) {
            __half o[4] = {__float2half_rn(xr[i].x), __float2half_rn(xr[i].y),
                           __float2half_rn(xr[i].z), __float2half_rn(xr[i].w)};
            *reinterpret_cast<uint2*>(xh + (lane + 32 * i) * 4) = *reinterpret_cast<uint2*>(o);
        }
    }

    float l[NEXP];
    #pragma unroll
    for (int e = 0; e < NEXP; e++) {
        const float4* w4 = reinterpret_cast<const float4*>(RW + e * HDIM);
        float s = 0.f;
        #pragma unroll
        for (int i = 0; i < 8; i++) {
            float4 b = w4[lane + 32 * i];
            s += xr[i].x * b.x + xr[i].y * b.y + xr[i].z * b.z + xr[i].w * b.w;
        }
        #pragma unroll
        for (int o = 16; o > 0; o >>= 1) s += __shfl_xor_sync(0xffffffffu, s, o);
        l[e] = s;
    }
    if (lane == 0) {
        int e0 = 0; float l0 = l[0];
        #pragma unroll
        for (int e = 1; e < NEXP; e++) { if (l[e] > l0) { l0 = l[e]; e0 = e; } }
        int e1 = -1; float l1 = -1e30f;
        #pragma unroll
        for (int e = 0; e < NEXP; e++) if (e != e0 && l[e] > l1) { l1 = l[e]; e1 = e; }
        float d  = __expf(l1 - l0);
        float w0 = 1.f / (1.f + d);
        float w1 = 1.f - w0;
        int n = gwarp;
        int p0 = atomicAdd(&g_count[e0], 1);
        g_perm[e0 * NTOK + p0] = n;
        g_tokexp[2*n] = e0; g_tokpos[2*n] = p0; g_tokw[2*n] = w0;
        int p1 = atomicAdd(&g_count[e1], 1);
        g_perm[e1 * NTOK + p1] = n;
        g_tokexp[2*n+1] = e1; g_tokpos[2*n+1] = p1; g_tokw[2*n+1] = w1;
    }
}

// ---------------- stage 1: h = silu(X@gateT)*(X@upT), fp16, 3-stage -------
// Block tile 128(M) x 128(I), BK=64. 8 warps 2(M)x4(N), warp tile 64x32 dual.
#define S1_A  0
#define S1_GH 16384
#define S1_UH 32768
#define S1_STG 49152
#define SMEM1 (3 * S1_STG)

__global__ __launch_bounds__(256, 1) void gemm1_kernel() {
    int e    = blockIdx.z;
    int M    = g_count[e];
    int row0 = blockIdx.y * 128;
    if (row0 >= M) return;
    int n0   = blockIdx.x * 128;
    int base = g_base[e];

    extern __shared__ char smem[];
    uint32_t sb = smem_u32(smem);
    int tid = threadIdx.x, warp = tid >> 5, lane = tid & 31;
    int m0  = (warp >> 2) * 64;   // 2 M-groups of 64
    int nn0 = (warp & 3) * 32;    // 4 N-groups of 32

    // cp.async setup: A 1024 chunks (4/thr); GH,UH 1024 chunks each (4/thr)
    const char* gpA[4]; uint32_t so[4];
    const char* gpB[4];
    #pragma unroll
    for (int i = 0; i < 4; i++) {
        int id = tid + 256 * i;
        int r = id >> 3, q = id & 7;
        so[i] = swoff(r, q * 16);
        int ar = row0 + r; if (ar > M - 1) ar = M - 1;
        int tok = g_perm[e * NTOK + ar];
        gpA[i] = (const char*)(g_Xh + (size_t)tok * HDIM) + q * 16;
        gpB[i] = (const char*)(g_Gh + ((size_t)e * IDIM + n0 + r) * HDIM) + q * 16;
    }
    const ptrdiff_t dUH = (const char*)g_Uh - (const char*)g_Gh;

    float accG[4][4][4], accU[4][4][4];
    #pragma unroll
    for (int a = 0; a < 4; a++)
        #pragma unroll
        for (int b = 0; b < 4; b++)
            #pragma unroll
            for (int c = 0; c < 4; c++) { accG[a][b][c] = 0.f; accU[a][b][c] = 0.f; }

    const int NC = HDIM / 64;   // 16

    #pragma unroll
    for (int p = 0; p < 2; p++) {
        uint32_t B = sb + p * S1_STG;
        ptrdiff_t off = (ptrdiff_t)p * 128;
        #pragma unroll
        for (int i = 0; i < 4; i++) {
            CP16(B + S1_A  + so[i], gpA[i] + off);
            CP16(B + S1_GH + so[i], gpB[i] + off);
            CP16(B + S1_UH + so[i], gpB[i] + dUH + off);
        }
        CP_COMMIT();
    }

    int sc = 0;
    for (int c = 0; c < NC; c++) {
        if (c + 1 < NC) { CP_WAIT1(); } else { CP_WAIT0(); }
        __syncthreads();

        if (c + 2 < NC) {
            int sn = sc + 2; if (sn >= 3) sn -= 3;
            uint32_t B = sb + sn * S1_STG;
            ptrdiff_t off = (ptrdiff_t)(c + 2) * 128;
            #pragma unroll
            for (int i = 0; i < 4; i++) {
                CP16(B + S1_A  + so[i], gpA[i] + off);
                CP16(B + S1_GH + so[i], gpB[i] + off);
                CP16(B + S1_UH + so[i], gpB[i] + dUH + off);
            }
            CP_COMMIT();
        }

        uint32_t SB = sb + sc * S1_STG;
        #pragma unroll
        for (int kk = 0; kk < 4; kk++) {
            int kb = kk * 32;
            uint32_t a[4][4];
            #pragma unroll
            for (int j = 0; j < 4; j++) ldm16x16(SB + S1_A, m0 + 16 * j, kb, lane, a[j]);
            uint32_t gh[2][4], uh[2][4];
            #pragma unroll
            for (int p = 0; p < 2; p++) {
                int nr = nn0 + p * 16;
                ldm16x16(SB + S1_GH, nr, kb, lane, gh[p]);
                ldm16x16(SB + S1_UH, nr, kb, lane, uh[p]);
            }
            #pragma unroll
            for (int nt = 0; nt < 4; nt++) {
                int p = nt >> 1, o = nt & 1;
                uint32_t bgh[2] = {gh[p][o], gh[p][o + 2]};
                uint32_t buh[2] = {uh[p][o], uh[p][o + 2]};
                #pragma unroll
                for (int mt = 0; mt < 4; mt++) {
                    mma_f16(accG[mt][nt], a[mt], bgh);
                    mma_f16(accU[mt][nt], a[mt], buh);
                }
            }
        }
        if (++sc >= 3) sc = 0;
    }

    // epilogue: h = silu(g) * u, write single fp16
    #pragma unroll
    for (int mt = 0; mt < 4; mt++) {
        #pragma unroll
        for (int nt = 0; nt < 4; nt++) {
            int col = n0 + nn0 + nt * 8 + (lane & 3) * 2;
            #pragma unroll
            for (int half = 0; half < 2; half++) {
                int r = row0 + m0 + mt * 16 + half * 8 + (lane >> 2);
                if (r < M) {
                    float g0 = accG[mt][nt][half * 2 + 0];
                    float g1 = accG[mt][nt][half * 2 + 1];
                    float u0 = accU[mt][nt][half * 2 + 0];
                    float u1 = accU[mt][nt][half * 2 + 1];
                    float h0 = (g0 / (1.f + __expf(-g0))) * u0;
                    float h1 = (g1 / (1.f + __expf(-g1))) * u1;
                    __half p[2] = {__float2half_rn(h0), __float2half_rn(h1)};
                    size_t gid = (size_t)(base + r) * IDIM + col;
                    *reinterpret_cast<uint32_t*>(&g_Hh[gid]) = *reinterpret_cast<uint32_t*>(p);
                }
            }
        }
    }
}

// ---------------- stage 2: Y = h @ downT (fp16, 3-stage) ----------------
// Block tile 256(M) x 128(H), BK=64. 8 warps 4(M)x2(N), warp tile 64x64.
#define S2_A  0
#define S2_BH 32768
#define S2_STG 49152
#define SMEM2 (3 * S2_STG)

__global__ __launch_bounds__(256, 1) void gemm2_kernel() {
    int e    = blockIdx.z;
    int M    = g_count[e];
    int row0 = blockIdx.y * 256;
    if (row0 >= M) return;
    int n0   = blockIdx.x * 128;
    int base = g_base[e];

    extern __shared__ char smem[];
    uint32_t sb = smem_u32(smem);
    int tid = threadIdx.x, warp = tid >> 5, lane = tid & 31;
    int m0  = (warp >> 1) * 64;   // 4 M-groups of 64
    int nn0 = (warp & 1) * 64;    // 2 N-groups of 64

    // A: 256 rows x 8 chunks = 2048 -> 8/thr; B: 128 rows x 8 = 1024 -> 4/thr
    const char* gpA[8]; uint32_t soA[8];
    #pragma unroll
    for (int i = 0; i < 8; i++) {
        int id = tid + 256 * i;
        int r = id >> 3, q = id & 7;
        soA[i] = swoff(r, q * 16);
        int ar = row0 + r; if (ar > M - 1) ar = M - 1;
        gpA[i] = (const char*)(g_Hh + (size_t)(base + ar) * IDIM) + q * 16;
    }
    const char* gpB[4]; uint32_t soB[4];
    #pragma unroll
    for (int i = 0; i < 4; i++) {
        int id = tid + 256 * i;
        int r = id >> 3, q = id & 7;
        soB[i] = swoff(r, q * 16);
        gpB[i] = (const char*)(g_Dh + ((size_t)e * HDIM + n0 + r) * IDIM) + q * 16;
    }

    float acc[4][8][4];
    #pragma unroll
    for (int a = 0; a < 4; a++)
        #pragma unroll
        for (int b = 0; b < 8; b++)
            #pragma unroll
            for (int c = 0; c < 4; c++) acc[a][b][c] = 0.f;

    const int NC = IDIM / 64;   // 32

    #pragma unroll
    for (int p = 0; p < 2; p++) {
        uint32_t B = sb + p * S2_STG;
        ptrdiff_t off = (ptrdiff_t)p * 128;
        #pragma unroll
        for (int i = 0; i < 8; i++) CP16(B + S2_A + soA[i], gpA[i] + off);
        #pragma unroll
        for (int i = 0; i < 4; i++) CP16(B + S2_BH + soB[i], gpB[i] + off);
        CP_COMMIT();
    }

    int sc = 0;
    for (int c = 0; c < NC; c++) {
        if (c + 1 < NC) { CP_WAIT1(); } else { CP_WAIT0(); }
        __syncthreads();

        if (c + 2 < NC) {
            int sn = sc + 2; if (sn >= 3) sn -= 3;
            uint32_t B = sb + sn * S2_STG;
            ptrdiff_t off = (ptrdiff_t)(c + 2) * 128;
            #pragma unroll
            for (int i = 0; i < 8; i++) CP16(B + S2_A + soA[i], gpA[i] + off);
            #pragma unroll
            for (int i = 0; i < 4; i++) CP16(B + S2_BH + soB[i], gpB[i] + off);
            CP_COMMIT();
        }

        uint32_t SB = sb + sc * S2_STG;
        #pragma unroll
        for (int kk = 0; kk < 4; kk++) {
            int kb = kk * 32;
            uint32_t a[4][4];
            #pragma unroll
            for (int j = 0; j < 4; j++) ldm16x16(SB + S2_A, m0 + 16 * j, kb, lane, a[j]);
            uint32_t bh[4][4];
            #pragma unroll
            for (int p = 0; p < 4; p++) ldm16x16(SB + S2_BH, nn0 + 16 * p, kb, lane, bh[p]);
            #pragma unroll
            for (int nt = 0; nt < 8; nt++) {
                int p = nt >> 1, o = nt & 1;
                uint32_t vh[2] = {bh[p][o], bh[p][o + 2]};
                #pragma unroll
                for (int mt = 0; mt < 4; mt++) {
                    mma_f16(acc[mt][nt], a[mt], vh);
                }
            }
        }
        if (++sc >= 3) sc = 0;
    }

    #pragma unroll
    for (int mt = 0; mt < 4; mt++) {
        #pragma unroll
        for (int nt = 0; nt < 8; nt++) {
            int col = n0 + nn0 + nt * 8 + (lane & 3) * 2;
            #pragma unroll
            for (int half = 0; half < 2; half++) {
                int r = row0 + m0 + mt * 16 + half * 8 + (lane >> 2);
                if (r < M) {
                    float2 o = make_float2(acc[mt][nt][half * 2 + 0], acc[mt][nt][half * 2 + 1]);
                    *reinterpret_cast<float2*>(&g_y[(size_t)(base + r) * HDIM + col]) = o;
                }
            }
        }
    }
}

// ---------------- combine ----------------
__global__ void combine_kernel(float* __restrict__ out) {
    int n = blockIdx.x;
    int c = threadIdx.x * 4;
    int e0 = g_tokexp[2*n],   p0 = g_tokpos[2*n];
    int e1 = g_tokexp[2*n+1], p1 = g_tokpos[2*n+1];
    float w0 = g_tokw[2*n], w1 = g_tokw[2*n+1];
    size_t gid0 = (size_t)(g_base[e0] + p0);
    size_t gid1 = (size_t)(g_base[e1] + p1);
    float4 y0 = *reinterpret_cast<const float4*>(&g_y[gid0 * HDIM + c]);
    float4 y1 = *reinterpret_cast<const float4*>(&g_y[gid1 * HDIM + c]);
    float4 o;
    o.x = w0 * y0.x + w1 * y1.x;
    o.y = w0 * y0.y + w1 * y1.y;
    o.z = w0 * y0.z + w1 * y1.z;
    o.w = w0 * y0.w + w1 * y1.w;
    *reinterpret_cast<float4*>(out + (size_t)n * HDIM + c) = o;
}

// ---------------- launch ----------------
extern "C" void kernel_launch(void* const* d_in, const int* in_sizes, int n_in,
                              void* d_out, int out_size) {
    const float* X  = (const float*)d_in[0];
    const float* RW = (const float*)d_in[1];
    const float* GW = (const float*)d_in[2];
    const float* UW = (const float*)d_in[3];
    const float* DW = (const float*)d_in[4];
    float* out = (float*)d_out;

    cudaFuncSetAttribute(gemm1_kernel, cudaFuncAttributeMaxDynamicSharedMemorySize, SMEM1);
    cudaFuncSetAttribute(gemm2_kernel, cudaFuncAttributeMaxDynamicSharedMemorySize, SMEM2);

    __half *gh, *uh, *dh;
    cudaGetSymbolAddress((void**)&gh, g_Gh);
    cudaGetSymbolAddress((void**)&uh, g_Uh);
    cudaGetSymbolAddress((void**)&dh, g_Dh);

    const int nW = NEXP * IDIM * HDIM / 4;
    convert1_kernel<<<(nW + 255) / 256, 256>>>(GW, gh, nW);
    convert1_kernel<<<(nW + 255) / 256, 256>>>(UW, uh, nW);
    convert1_kernel<<<(nW + 255) / 256, 256>>>(DW, dh, nW);

    zero_counts_kernel<<<1, 32>>>();
    router_kernel<<<NTOK / 8, 256>>>(X, RW);   // also writes g_Xh
    scan_base_kernel<<<1, 1>>>();

    { dim3 g(IDIM / 128, NTOK / 128, NEXP); gemm1_kernel<<<g, 256, SMEM1>>>(); }
    { dim3 g(HDIM / 128, NTOK / 256, NEXP); gemm2_kernel<<<g, 256, SMEM2>>>(); }
    combine_kernel<<<NTOK, 256>>>(out);
}